// round 11
// baseline (speedup 1.0000x reference)
#include <cuda_runtime.h>
#include <cuda_bf16.h>
#include <mma.h>
#include <cstdint>

using namespace nvcuda;

// Problem constants
#define BATCH   4
#define SQ      4096
#define SK      1024
#define D_EMB   1024
#define D_CRUZ  768
#define N_HEADS 16
#define D_HEAD  64

// Scratch (static device allocations — allowed)
__device__ float g_q[BATCH * SQ * D_EMB];     // 64 MB
__device__ float g_k[BATCH * SK * D_EMB];     // 16 MB
__device__ float g_v[BATCH * SK * D_EMB];     // 16 MB
__device__ float g_attn[BATCH * SQ * D_EMB];  // 64 MB
// tf32-pre-rounded inputs/weights
__device__ float g_xr[BATCH * SQ * D_EMB];    // 64 MB
__device__ float g_yr[BATCH * SK * D_CRUZ];   // 12 MB
__device__ float g_wq[D_EMB * D_EMB];         // 4 MB
__device__ float g_wk[D_CRUZ * D_EMB];        // 3 MB
__device__ float g_wv[D_CRUZ * D_EMB];        // 3 MB
__device__ float g_wo[D_EMB * D_EMB];         // 4 MB

// ---------------------------------------------------------------------------
// helpers
// ---------------------------------------------------------------------------
__device__ __forceinline__ void cp_async16(float* dst_smem, const float* src) {
    unsigned int d = (unsigned int)__cvta_generic_to_shared(dst_smem);
    asm volatile("cp.async.ca.shared.global [%0], [%1], 16;\n" :: "r"(d), "l"(src));
}
__device__ __forceinline__ void cp_commit() {
    asm volatile("cp.async.commit_group;\n");
}
template <int N>
__device__ __forceinline__ void cp_wait() {
    asm volatile("cp.async.wait_group %0;\n" :: "n"(N));
}

__device__ __forceinline__ uint32_t f2tf(float f) {
    uint32_t u;
    asm("cvt.rna.tf32.f32 %0, %1;" : "=r"(u) : "f"(f));
    return u;
}
__device__ __forceinline__ float roundtf(float f) {
    return __uint_as_float(f2tf(f));
}

// mma.m16n8k8 tf32 (verified layouts; gid=lane>>2, tig=lane&3):
//   A: a0=(gid,tig) a1=(gid+8,tig) a2=(gid,tig+4) a3=(gid+8,tig+4)
//   B: b0=(k=tig,n=gid) b1=(k=tig+4,n=gid)
//   C: c0=(gid,2tig) c1=(gid,2tig+1) c2=(gid+8,2tig) c3=(gid+8,2tig+1)
__device__ __forceinline__ void mma_tf32(float* d, const uint32_t* a,
                                         uint32_t b0, uint32_t b1) {
    asm volatile(
        "mma.sync.aligned.m16n8k8.row.col.f32.tf32.tf32.f32 "
        "{%0,%1,%2,%3}, {%4,%5,%6,%7}, {%8,%9}, {%0,%1,%2,%3};"
        : "+f"(d[0]), "+f"(d[1]), "+f"(d[2]), "+f"(d[3])
        : "r"(a[0]), "r"(a[1]), "r"(a[2]), "r"(a[3]), "r"(b0), "r"(b1));
}

// ---------------------------------------------------------------------------
// Pre-round: convert x, y, and the four weight matrices to tf32-rounded fp32.
// ---------------------------------------------------------------------------
#define SEG_X  4194304
#define SEG_Y  (SEG_X + 786432)
#define SEG_WQ (SEG_Y + 262144)
#define SEG_WK (SEG_WQ + 196608)
#define SEG_WV (SEG_WK + 196608)
#define SEG_WO (SEG_WV + 262144)

__global__ __launch_bounds__(256)
void preround_all(const float4* __restrict__ x, const float4* __restrict__ y,
                  const float4* __restrict__ wq, const float4* __restrict__ wk,
                  const float4* __restrict__ wv, const float4* __restrict__ wo,
                  float4* __restrict__ xr, float4* __restrict__ yr,
                  float4* __restrict__ wqr, float4* __restrict__ wkr,
                  float4* __restrict__ wvr, float4* __restrict__ wor) {
    for (long i = (long)blockIdx.x * blockDim.x + threadIdx.x; i < SEG_WO;
         i += (long)gridDim.x * blockDim.x) {
        const float4* src; float4* dst; long o;
        if (i < SEG_X)       { src = x;  dst = xr;  o = i; }
        else if (i < SEG_Y)  { src = y;  dst = yr;  o = i - SEG_X; }
        else if (i < SEG_WQ) { src = wq; dst = wqr; o = i - SEG_Y; }
        else if (i < SEG_WK) { src = wk; dst = wkr; o = i - SEG_WQ; }
        else if (i < SEG_WV) { src = wv; dst = wvr; o = i - SEG_WK; }
        else                 { src = wo; dst = wor; o = i - SEG_WV; }
        float4 v = src[o];
        v.x = roundtf(v.x); v.y = roundtf(v.y);
        v.z = roundtf(v.z); v.w = roundtf(v.w);
        dst[o] = v;
    }
}

// ---------------------------------------------------------------------------
// GEMM v3 (unchanged): 128x128x32 tf32, 2-stage cp.async, pre-rounded inputs.
// ---------------------------------------------------------------------------
#define BM 128
#define BN 128
#define BK 32
#define LDA 40
#define LDB 136
#define A_STG (BM * LDA)
#define B_STG (BK * LDB)
#define STG_FLOATS (A_STG + B_STG)
#define GEMM_SMEM_BYTES (2 * STG_FLOATS * 4)

template <bool ROUND_OUT>
__global__ __launch_bounds__(256)
void gemm_bias_tf32_v3(const float* __restrict__ A, const float* __restrict__ W,
                       const float* __restrict__ bias, float* __restrict__ C,
                       int M, int N, int K) {
    extern __shared__ float sm[];
    const int tid  = threadIdx.x;
    const int warp = tid >> 5;
    const int wm   = warp >> 1;
    const int wn   = warp & 1;
    const int bm   = blockIdx.y * BM;
    const int bn   = blockIdx.x * BN;

    wmma::fragment<wmma::accumulator, 16, 16, 8, float> acc[2][4];
#pragma unroll
    for (int r = 0; r < 2; r++)
#pragma unroll
        for (int c = 0; c < 4; c++) wmma::fill_fragment(acc[r][c], 0.0f);

    auto issue = [&](int kt, int buf) {
        float* As = sm + buf * STG_FLOATS;
        float* Bs = As + A_STG;
        const float* Ag = A + (size_t)bm * K + kt * BK;
        const float* Wg = W + (size_t)(kt * BK) * N + bn;
#pragma unroll
        for (int i = 0; i < 4; i++) {
            int p   = tid + i * 256;
            int row = p >> 3;
            int col = (p & 7) * 4;
            cp_async16(&As[row * LDA + col], Ag + (size_t)row * K + col);
        }
#pragma unroll
        for (int i = 0; i < 4; i++) {
            int p   = tid + i * 256;
            int row = p >> 5;
            int col = (p & 31) * 4;
            cp_async16(&Bs[row * LDB + col], Wg + (size_t)row * N + col);
        }
    };

    const int NK = K / BK;
    issue(0, 0);
    cp_commit();

    for (int kt = 0; kt < NK; kt++) {
        if (kt + 1 < NK) {
            issue(kt + 1, (kt + 1) & 1);
            cp_commit();
            cp_wait<1>();
        } else {
            cp_wait<0>();
        }
        __syncthreads();

        float* As = sm + (kt & 1) * STG_FLOATS;
        float* Bs = As + A_STG;
#pragma unroll
        for (int kk = 0; kk < BK; kk += 8) {
            wmma::fragment<wmma::matrix_a, 16, 16, 8, wmma::precision::tf32, wmma::row_major> a[2];
#pragma unroll
            for (int r = 0; r < 2; r++)
                wmma::load_matrix_sync(a[r], &As[(wm * 32 + r * 16) * LDA + kk], LDA);
#pragma unroll
            for (int c = 0; c < 4; c++) {
                wmma::fragment<wmma::matrix_b, 16, 16, 8, wmma::precision::tf32, wmma::row_major> b;
                wmma::load_matrix_sync(b, &Bs[kk * LDB + wn * 64 + c * 16], LDB);
#pragma unroll
                for (int r = 0; r < 2; r++)
                    wmma::mma_sync(acc[r][c], a[r], b, acc[r][c]);
            }
        }
        __syncthreads();
    }

    float* Cs = sm;
#pragma unroll
    for (int r = 0; r < 2; r++)
#pragma unroll
        for (int c = 0; c < 4; c++)
            wmma::store_matrix_sync(&Cs[(wm * 32 + r * 16) * LDB + wn * 64 + c * 16],
                                    acc[r][c], LDB, wmma::mem_row_major);
    __syncthreads();

#pragma unroll
    for (int i = 0; i < 16; i++) {
        int p   = tid + i * 256;
        int row = p >> 5;
        int col = (p & 31) * 4;
        float4 v = *reinterpret_cast<float4*>(&Cs[row * LDB + col]);
        float4 bb = *reinterpret_cast<const float4*>(&bias[bn + col]);
        v.x += bb.x; v.y += bb.y; v.z += bb.z; v.w += bb.w;
        if (ROUND_OUT) {
            v.x = roundtf(v.x); v.y = roundtf(v.y);
            v.z = roundtf(v.z); v.w = roundtf(v.w);
        }
        *reinterpret_cast<float4*>(&C[(size_t)(bm + row) * N + bn + col]) = v;
    }
}

// ---------------------------------------------------------------------------
// Flash attention v8: identical math to v7; LDQ 76->68 shrinks smem to
// 110.6 KB => 2 CTAs/SM (doubled issue capacity). Bank-conflict audit:
//   Q frag read bank = (4*gid + tig [+4] + 8kc) mod 32 -> 32 distinct ✓
//   K frag read bank = (12*gid + tig [+4]) mod 32      -> 32 distinct ✓
//   V frag read bank = (8*tig + gid) mod 32            -> 32 distinct ✓
// ---------------------------------------------------------------------------
#define QT 128
#define KT 64
#define LDQ 68
#define LDK 76
#define LDV 72
#define QS_FL (QT * LDQ)                        // 8704
#define KS_FL (KT * LDK)                        // 4864
#define VS_FL (KT * LDV)                        // 4608
#define ATTN_SMEM_FLOATS (QS_FL + 2 * KS_FL + 2 * VS_FL)
#define ATTN_SMEM_BYTES  (ATTN_SMEM_FLOATS * 4) // 110592 B

__global__ __launch_bounds__(256, 2)
void attn_fa2_tf32(const float* __restrict__ qg, const float* __restrict__ kg,
                   const float* __restrict__ vg, float* __restrict__ og) {
    extern __shared__ float smem[];
    float* Qs = smem;                           // 128 x 68
    float* Kb = Qs + QS_FL;                     // 2 x 64 x 76
    float* Vb = Kb + 2 * KS_FL;                 // 2 x 64 x 72

    const int tid  = threadIdx.x;
    const int warp = tid >> 5;
    const int lane = tid & 31;
    const int gid  = lane >> 2;
    const int tig  = lane & 3;
    const int q0 = blockIdx.x * QT;
    const int h  = blockIdx.y;
    const int b  = blockIdx.z;
    const float scale = 0.125f;                 // power of 2: preserves tf32 rounding

    // Stage Q tile (128x64 = 2048 float4), pre-scaled
#pragma unroll
    for (int i = 0; i < 8; i++) {
        int p   = tid + i * 256;
        int row = p >> 4;
        int col = (p & 15) * 4;
        float4 v = *reinterpret_cast<const float4*>(
            &qg[((size_t)(b * SQ + q0 + row)) * D_EMB + h * D_HEAD + col]);
        v.x *= scale; v.y *= scale; v.z *= scale; v.w *= scale;
        *reinterpret_cast<float4*>(&Qs[row * LDQ + col]) = v;
    }
    __syncthreads();

    // Q A-fragments (raw bits — already tf32)
    const int r0 = warp * 16 + gid;
    uint32_t qf[8][4];
#pragma unroll
    for (int kc = 0; kc < 8; kc++) {
        qf[kc][0] = __float_as_uint(Qs[r0 * LDQ + kc * 8 + tig]);
        qf[kc][1] = __float_as_uint(Qs[(r0 + 8) * LDQ + kc * 8 + tig]);
        qf[kc][2] = __float_as_uint(Qs[r0 * LDQ + kc * 8 + tig + 4]);
        qf[kc][3] = __float_as_uint(Qs[(r0 + 8) * LDQ + kc * 8 + tig + 4]);
    }

    float o[8][4];
#pragma unroll
    for (int j = 0; j < 8; j++)
#pragma unroll
        for (int e = 0; e < 4; e++) o[j][e] = 0.0f;
    float m0 = -1e30f, m1 = -1e30f, l0 = 0.0f, l1 = 0.0f;

    auto issue_kv = [&](int kt, int buf) {
        const int k0 = kt * KT;
        float* Ks = Kb + buf * KS_FL;
        float* Vs = Vb + buf * VS_FL;
#pragma unroll
        for (int i = 0; i < 4; i++) {
            int p   = tid + i * 256;
            int row = p >> 4;
            int col = (p & 15) * 4;
            size_t g = ((size_t)(b * SK + k0 + row)) * D_EMB + h * D_HEAD + col;
            cp_async16(&Ks[row * LDK + col], &kg[g]);
            cp_async16(&Vs[row * LDV + col], &vg[g]);
        }
    };

    issue_kv(0, 0);
    cp_commit();

    const int NKT = SK / KT;
    for (int kt = 0; kt < NKT; kt++) {
        if (kt + 1 < NKT) {
            issue_kv(kt + 1, (kt + 1) & 1);
            cp_commit();
            cp_wait<1>();
        } else {
            cp_wait<0>();
        }
        __syncthreads();

        const float* Ks = Kb + (kt & 1) * KS_FL;
        const float* Vs = Vb + (kt & 1) * VS_FL;

        // ---- S = Q @ K^T ----
        float s[8][4];
#pragma unroll
        for (int j = 0; j < 8; j++)
#pragma unroll
            for (int e = 0; e < 4; e++) s[j][e] = 0.0f;

#pragma unroll
        for (int kc = 0; kc < 8; kc++) {
#pragma unroll
            for (int j = 0; j < 8; j++) {
                uint32_t b0 = __float_as_uint(Ks[(j * 8 + gid) * LDK + kc * 8 + tig]);
                uint32_t b1 = __float_as_uint(Ks[(j * 8 + gid) * LDK + kc * 8 + tig + 4]);
                mma_tf32(s[j], qf[kc], b0, b1);
            }
        }

        // ---- online softmax ----
        float mx0 = -1e30f, mx1 = -1e30f;
#pragma unroll
        for (int j = 0; j < 8; j++) {
            mx0 = fmaxf(mx0, fmaxf(s[j][0], s[j][1]));
            mx1 = fmaxf(mx1, fmaxf(s[j][2], s[j][3]));
        }
        mx0 = fmaxf(mx0, __shfl_xor_sync(0xffffffffu, mx0, 1));
        mx0 = fmaxf(mx0, __shfl_xor_sync(0xffffffffu, mx0, 2));
        mx1 = fmaxf(mx1, __shfl_xor_sync(0xffffffffu, mx1, 1));
        mx1 = fmaxf(mx1, __shfl_xor_sync(0xffffffffu, mx1, 2));

        const float mn0 = fmaxf(m0, mx0);
        const float mn1 = fmaxf(m1, mx1);
        float sum0 = 0.0f, sum1 = 0.0f;
#pragma unroll
        for (int j = 0; j < 8; j++) {
            s[j][0] = __expf(s[j][0] - mn0);
            s[j][1] = __expf(s[j][1] - mn0);
            s[j][2] = __expf(s[j][2] - mn1);
            s[j][3] = __expf(s[j][3] - mn1);
            sum0 += s[j][0] + s[j][1];
            sum1 += s[j][2] + s[j][3];
        }
        sum0 += __shfl_xor_sync(0xffffffffu, sum0, 1);
        sum0 += __shfl_xor_sync(0xffffffffu, sum0, 2);
        sum1 += __shfl_xor_sync(0xffffffffu, sum1, 1);
        sum1 += __shfl_xor_sync(0xffffffffu, sum1, 2);

        const float al0 = __expf(m0 - mn0);
        const float al1 = __expf(m1 - mn1);
        l0 = l0 * al0 + sum0;
        l1 = l1 * al1 + sum1;
        m0 = mn0; m1 = mn1;

#pragma unroll
        for (int j = 0; j < 8; j++) {
            o[j][0] *= al0; o[j][1] *= al0;
            o[j][2] *= al1; o[j][3] *= al1;
        }

        // ---- permute P: C layout -> A layout (shuffles), cvt once ----
        uint32_t pa[8][4];
        const int srcA = (lane & ~3) | (tig >> 1);
        const int srcB = (lane & ~3) | (2 + (tig >> 1));
        const bool oddc = (tig & 1);
#pragma unroll
        for (int j = 0; j < 8; j++) {
            float x0 = __shfl_sync(0xffffffffu, s[j][0], srcA);
            float x1 = __shfl_sync(0xffffffffu, s[j][1], srcA);
            float y0 = __shfl_sync(0xffffffffu, s[j][0], srcB);
            float y1 = __shfl_sync(0xffffffffu, s[j][1], srcB);
            float z0 = __shfl_sync(0xffffffffu, s[j][2], srcA);
            float z1 = __shfl_sync(0xffffffffu, s[j][3], srcA);
            float w0 = __shfl_sync(0xffffffffu, s[j][2], srcB);
            float w1 = __shfl_sync(0xffffffffu, s[j][3], srcB);
            pa[j][0] = f2tf(oddc ? x1 : x0);
            pa[j][1] = f2tf(oddc ? z1 : z0);
            pa[j][2] = f2tf(oddc ? y1 : y0);
            pa[j][3] = f2tf(oddc ? w1 : w0);
        }

        // ---- O += P @ V ----
#pragma unroll
        for (int kc = 0; kc < 8; kc++) {
#pragma unroll
            for (int j = 0; j < 8; j++) {
                uint32_t b0 = __float_as_uint(Vs[(kc * 8 + tig) * LDV + j * 8 + gid]);
                uint32_t b1 = __float_as_uint(Vs[(kc * 8 + tig + 4) * LDV + j * 8 + gid]);
                mma_tf32(o[j], pa[kc], b0, b1);
            }
        }
        __syncthreads();
    }

    // ---- epilogue: (O / l) rounded to tf32 for the O-projection ----
    const float inv0 = 1.0f / l0;
    const float inv1 = 1.0f / l1;
    const size_t rowbase0 = ((size_t)(b * SQ + q0 + r0)) * D_EMB + h * D_HEAD;
    const size_t rowbase1 = rowbase0 + 8 * D_EMB;
#pragma unroll
    for (int j = 0; j < 8; j++) {
        int col = j * 8 + 2 * tig;
        *reinterpret_cast<float2*>(&og[rowbase0 + col]) =
            make_float2(roundtf(o[j][0] * inv0), roundtf(o[j][1] * inv0));
        *reinterpret_cast<float2*>(&og[rowbase1 + col]) =
            make_float2(roundtf(o[j][2] * inv1), roundtf(o[j][3] * inv1));
    }
}

// ---------------------------------------------------------------------------
// Launcher
// ---------------------------------------------------------------------------
extern "C" void kernel_launch(void* const* d_in, const int* in_sizes, int n_in,
                              void* d_out, int out_size) {
    const float* x  = (const float*)d_in[0];
    const float* y  = (const float*)d_in[1];
    const float* Wq = (const float*)d_in[2];
    const float* bq = (const float*)d_in[3];
    const float* Wk = (const float*)d_in[4];
    const float* bk = (const float*)d_in[5];
    const float* Wv = (const float*)d_in[6];
    const float* bv = (const float*)d_in[7];
    const float* Wo = (const float*)d_in[8];
    const float* bo = (const float*)d_in[9];
    float* out = (float*)d_out;

    float *gq, *gk, *gv, *ga, *xr, *yr, *wqr, *wkr, *wvr, *wor;
    cudaGetSymbolAddress((void**)&gq, g_q);
    cudaGetSymbolAddress((void**)&gk, g_k);
    cudaGetSymbolAddress((void**)&gv, g_v);
    cudaGetSymbolAddress((void**)&ga, g_attn);
    cudaGetSymbolAddress((void**)&xr, g_xr);
    cudaGetSymbolAddress((void**)&yr, g_yr);
    cudaGetSymbolAddress((void**)&wqr, g_wq);
    cudaGetSymbolAddress((void**)&wkr, g_wk);
    cudaGetSymbolAddress((void**)&wvr, g_wv);
    cudaGetSymbolAddress((void**)&wor, g_wo);

    cudaFuncSetAttribute(gemm_bias_tf32_v3<true>,
                         cudaFuncAttributeMaxDynamicSharedMemorySize, GEMM_SMEM_BYTES);
    cudaFuncSetAttribute(gemm_bias_tf32_v3<false>,
                         cudaFuncAttributeMaxDynamicSharedMemorySize, GEMM_SMEM_BYTES);
    cudaFuncSetAttribute(attn_fa2_tf32,
                         cudaFuncAttributeMaxDynamicSharedMemorySize, ATTN_SMEM_BYTES);

    // Pre-round inputs + weights to tf32
    preround_all<<<2048, 256>>>((const float4*)x, (const float4*)y,
                                (const float4*)Wq, (const float4*)Wk,
                                (const float4*)Wv, (const float4*)Wo,
                                (float4*)xr, (float4*)yr, (float4*)wqr,
                                (float4*)wkr, (float4*)wvr, (float4*)wor);

    // Projections (outputs tf32-rounded: consumed as tf32 by attention)
    gemm_bias_tf32_v3<true><<<dim3(D_EMB / BN, (BATCH * SQ) / BM), 256, GEMM_SMEM_BYTES>>>(
        xr, wqr, bq, gq, BATCH * SQ, D_EMB, D_EMB);
    gemm_bias_tf32_v3<true><<<dim3(D_EMB / BN, (BATCH * SK) / BM), 256, GEMM_SMEM_BYTES>>>(
        yr, wkr, bk, gk, BATCH * SK, D_EMB, D_CRUZ);
    gemm_bias_tf32_v3<true><<<dim3(D_EMB / BN, (BATCH * SK) / BM), 256, GEMM_SMEM_BYTES>>>(
        yr, wvr, bv, gv, BATCH * SK, D_EMB, D_CRUZ);

    // Attention (register-resident FA2, 2 CTAs/SM)
    attn_fa2_tf32<<<dim3(SQ / QT, N_HEADS, BATCH), 256, ATTN_SMEM_BYTES>>>(gq, gk, gv, ga);

    // Output projection (full-precision fp32 output)
    gemm_bias_tf32_v3<false><<<dim3(D_EMB / BN, (BATCH * SQ) / BM), 256, GEMM_SMEM_BYTES>>>(
        ga, wor, bo, out, BATCH * SQ, D_EMB, D_EMB);
}